// round 13
// baseline (speedup 1.0000x reference)
#include <cuda_runtime.h>
#include <cuda_fp16.h>
#include <cstdint>
#include <cstddef>

// ============================================================================
// Problem constants
// ============================================================================
#define NT      8192            // n_test == n_train
#define NF      64              // n_feat
#define KD      384             // GEMM K = 64 feat * 3 Fourier dims * 2 (hi/lo)
#define BM      128             // CTA M tile
#define BN      128             // CTA N tile
#define BK      64              // halfs per K chunk (128 bytes/row)
#define NCHUNK  (KD / BK)       // 6
#define NSTAGE  3

#define NSTRIP  (NT / BM)       // 64 row strips
#define NCOLT   (NT / BN)       // 64 col tiles per strip
#define NSTRIPW 4               // strips per wave
#define GRID    (NSTRIPW * NCOLT)   // 256 CTAs, all resident (2/SM proven)
#define NWAVE   (NSTRIP / NSTRIPW)  // 16

// SMEM: three stages of (A tile 16KB + B tile 16KB)
#define STAGE_BYTES (BM * 128 + BN * 128)           // 32768
#define SM_A(s)     ((s) * STAGE_BYTES)
#define SM_B(s)     ((s) * STAGE_BYTES + BM * 128)
#define SMEM_TOTAL  (NSTAGE * STAGE_BYTES)          // 98304 (x2 CTAs = 192KB/SM)

// ============================================================================
// Device scratch (no allocations allowed)
// ============================================================================
__device__ __align__(1024) __half g_A[(size_t)NT * KD];   // 6 MB Fourier pack (test, weighted)
__device__ __align__(1024) __half g_B[(size_t)NT * KD];   // 6 MB Fourier pack (train)
__device__ unsigned g_rowmax[NT];                          // bits of (rowmax_log + 128)
__device__ float    g_base;                                // -64*ln3 + 0.25*sum(w)
__device__ int      g_done[NSTRIP];                        // completed tiles per strip

// ============================================================================
// Helpers
// ============================================================================
__device__ __forceinline__ uint32_t smem_u32(const void* p) {
    uint32_t a;
    asm("{ .reg .u64 t; cvta.to.shared.u64 t, %1; cvt.u32.u64 %0, t; }"
        : "=r"(a) : "l"(p));
    return a;
}

__device__ __forceinline__ uint32_t sw128(uint32_t off) {
    return off ^ ((off >> 3) & 0x70u);
}

__device__ __forceinline__ void cp16(uint32_t smem_dst, const void* gmem_src) {
    asm volatile("cp.async.cg.shared.global [%0], [%1], 16;"
                 :: "r"(smem_dst), "l"(gmem_src) : "memory");
}

__device__ __forceinline__ void ldm4(uint32_t* r, uint32_t addr) {
    asm volatile("ldmatrix.sync.aligned.m8n8.x4.shared.b16 {%0,%1,%2,%3}, [%4];"
                 : "=r"(r[0]), "=r"(r[1]), "=r"(r[2]), "=r"(r[3]) : "r"(addr));
}

__device__ __forceinline__ void mma16816(float* d, const uint32_t* a, const uint32_t* b) {
    asm volatile(
        "mma.sync.aligned.m16n8k16.row.col.f32.f16.f16.f32 "
        "{%0,%1,%2,%3}, {%4,%5,%6,%7}, {%8,%9}, {%0,%1,%2,%3};"
        : "+f"(d[0]), "+f"(d[1]), "+f"(d[2]), "+f"(d[3])
        : "r"(a[0]), "r"(a[1]), "r"(a[2]), "r"(a[3]), "r"(b[0]), "r"(b[1]));
}

// sign-apply on fp16 bits: sgn in {-1,0,+1}
__device__ __forceinline__ unsigned short sgn16(unsigned short v, int sgn) {
    return sgn == 0 ? (unsigned short)0
                    : (sgn > 0 ? v : (unsigned short)(v ^ 0x8000u));
}

// ============================================================================
// Kernel 1: Fourier pack + state reset + base reduction  (proven R6-R12)
// ============================================================================
__global__ __launch_bounds__(256) void pack_kernel(
    const float* __restrict__ bw,
    const float* __restrict__ testX,
    const float* __restrict__ trainX)
{
    int idx = blockIdx.x * 256 + threadIdx.x;     // 0 .. NT*NF-1
    if (idx < NT) g_rowmax[idx] = 0u;             // stored values always > 0
    if (idx < NSTRIP) g_done[idx] = 0;

    __shared__ float sw[NF];
    if (blockIdx.x == 0) {
        if (threadIdx.x < NF) {
            float h = bw[threadIdx.x];
            sw[threadIdx.x] = logf(3.0f * (1.0f - h) / h);
        }
        __syncthreads();
        if (threadIdx.x == 0) {
            float s = 0.0f;
            #pragma unroll
            for (int f = 0; f < NF; f++) s += sw[f];
            g_base = -64.0f * 1.0986122886681098f + 0.25f * s;
        }
    }

    if (idx >= NT * NF) return;
    int i = idx >> 6;
    int f = idx & (NF - 1);

    float h = bw[f];
    float w = logf(3.0f * (1.0f - h) / h);        // log_true - log_false (> 0)
    float w2 = 0.5f * w, w4 = 0.25f * w;
    __half h2 = __float2half_rn(w2);
    unsigned short H2 = __half_as_ushort(h2);
    unsigned short L2 = __half_as_ushort(__float2half_rn(w2 - __half2float(h2)));
    __half h4 = __float2half_rn(w4);
    unsigned short H4 = __half_as_ushort(h4);
    unsigned short L4 = __half_as_ushort(__float2half_rn(w4 - __half2float(h4)));

    int t = (int)testX[idx];
    int s = (int)trainX[idx];

    int ct = (t == 0) ? 1 : ((t == 2) ? -1 : 0);
    int st = (t == 1) ? 1 : ((t == 3) ? -1 : 0);
    int pt = (t & 1) ? -1 : 1;
    int cs = (s == 0) ? 1 : ((s == 2) ? -1 : 0);
    int ss = (s == 1) ? 1 : ((s == 3) ? -1 : 0);
    int ps = (s & 1) ? -1 : 1;

    const unsigned short ONE = 0x3C00u;
    unsigned short a0 = sgn16(H2, ct), a1 = sgn16(L2, ct);
    unsigned short a2 = sgn16(H2, st), a3 = sgn16(L2, st);
    unsigned short a4 = sgn16(H4, pt), a5 = sgn16(L4, pt);
    unsigned short bc = sgn16(ONE, cs), bs = sgn16(ONE, ss), bp = sgn16(ONE, ps);

    uint32_t* pa = reinterpret_cast<uint32_t*>(
        reinterpret_cast<char*>(g_A) + (size_t)i * (KD * 2) + f * 12);
    uint32_t* pb = reinterpret_cast<uint32_t*>(
        reinterpret_cast<char*>(g_B) + (size_t)i * (KD * 2) + f * 12);
    pa[0] = (uint32_t)a0 | ((uint32_t)a1 << 16);
    pa[1] = (uint32_t)a2 | ((uint32_t)a3 << 16);
    pa[2] = (uint32_t)a4 | ((uint32_t)a5 << 16);
    pb[0] = (uint32_t)bc | ((uint32_t)bc << 16);
    pb[1] = (uint32_t)bs | ((uint32_t)bs << 16);
    pb[2] = (uint32_t)bp | ((uint32_t)bp << 16);
}

// ============================================================================
// Kernel 2: single-pass GEMM with lag-1 deferred exp epilogue
//   256 persistent CTAs = 16 waves x (4 strips x 64 col tiles).
//   Wave w: GEMM -> prefetch w+1 -> write log_dist -> rowmax+signal
//           -> fixup own tile of wave w-1 (strip already complete).
// ============================================================================
__global__ __launch_bounds__(256, 2) void gemm_fused_kernel(float* __restrict__ out)
{
    extern __shared__ __align__(1024) unsigned char smem[];
    __shared__ float s_rm[BM];
    const int tid  = threadIdx.x;
    const int wid  = tid >> 5;
    const int lane = tid & 31;
    const int wm   = wid >> 1;           // warp M index 0..3  (rows wm*32)
    const int wn   = wid & 1;            // warp N index 0..1  (cols wn*64)
    const int sIdx = blockIdx.x >> 6;    // strip-within-wave 0..3
    const int col  = blockIdx.x & 63;    // column tile (constant across waves)
    const int n0   = col * BN;

    const uint32_t sbase = smem_u32(smem);
    const float BASEV = g_base;
    const __half* gB = g_B + (size_t)n0 * KD;    // constant across waves

    #define LOAD_CHUNK(pA, pB, c, s)                                            \
    do {                                                                        \
        uint32_t aB = sbase + SM_A(s), bB = sbase + SM_B(s);                    \
        _Pragma("unroll")                                                       \
        for (int i = 0; i < 8; i++) {                                           \
            int u = tid + i * 256;                                              \
            if (u < 1024) {                                                     \
                int row = u >> 3, seg = u & 7;                                  \
                cp16(aB + sw128(row * 128 + seg * 16),                          \
                     (pA) + (size_t)row * KD + (c) * BK + seg * 8);             \
            } else {                                                            \
                int u2 = u - 1024;                                              \
                int row = u2 >> 3, seg = u2 & 7;                                \
                cp16(bB + sw128(row * 128 + seg * 16),                          \
                     (pB) + (size_t)row * KD + (c) * BK + seg * 8);             \
            }                                                                   \
        }                                                                       \
        asm volatile("cp.async.commit_group;");                                 \
    } while (0)

    // ---- per-lane ldmatrix geometry (proven R5-R12) ----
    const int aRow   = wm * 32 + ((lane >> 3) & 1) * 8 + (lane & 7);
    const int aKhalf = (lane >> 4) & 1;
    const int arow7  = aRow & 7;
    const int bRowIn = ((lane >> 4) & 1) * 8 + (lane & 7);
    const int bKhalf = (lane >> 3) & 1;
    const int brow7  = bRowIn & 7;
    const int g  = lane >> 2;
    const int q  = lane & 3;

    // ---- fixup of own tile for strip `prev` (lag-1; strip usually done) ----
    #define FIXUP(prevStrip)                                                    \
    do {                                                                        \
        const int pm0 = (prevStrip) * BM;                                       \
        if (tid == 0) {                                                         \
            while (atomicAdd(&g_done[(prevStrip)], 0) < NCOLT) { }              \
            __threadfence();                                                    \
        }                                                                       \
        __syncthreads();                                                        \
        if (tid < BM) {                                                         \
            unsigned bits = atomicOr(&g_rowmax[pm0 + tid], 0u);                 \
            s_rm[tid] = __uint_as_float(bits) - 128.0f;                         \
        }                                                                       \
        __syncthreads();                                                        \
        {                                                                       \
            const int c4 = tid & 31;          /* float4 col 0..31 */            \
            const int rb = tid >> 5;          /* row base 0..7   */             \
            _Pragma("unroll")                                                   \
            for (int it = 0; it < 16; it++) {                                   \
                const int lr = rb + it * 8;                                     \
                const float m = s_rm[lr];                                       \
                float4* p = reinterpret_cast<float4*>(                          \
                    out + (size_t)(pm0 + lr) * NT + n0) + c4;                   \
                float4 v = *p;                                                  \
                v.x = m * __expf(v.x - m);                                      \
                v.y = m * __expf(v.y - m);                                      \
                v.z = m * __expf(v.z - m);                                      \
                v.w = m * __expf(v.w - m);                                      \
                *p = v;                                                         \
            }                                                                   \
        }                                                                       \
        __syncthreads();                                                        \
    } while (0)

    {   // prefetch wave 0 chunks 0,1
        const __half* gA0 = g_A + (size_t)(sIdx * BM) * KD;
        LOAD_CHUNK(gA0, gB, 0, 0);
        LOAD_CHUNK(gA0, gB, 1, 1);
    }

    for (int w = 0; w < NWAVE; w++) {
        const int strip = w * NSTRIPW + sIdx;
        const int m0 = strip * BM;
        const __half* gA = g_A + (size_t)m0 * KD;

        float acc[2][8][4];
        #pragma unroll
        for (int t = 0; t < 2; t++)
            #pragma unroll
            for (int j = 0; j < 8; j++)
                #pragma unroll
                for (int v = 0; v < 4; v++) acc[t][j][v] = 0.0f;

        for (int c = 0; c < NCHUNK; c++) {
            if (c + 2 < NCHUNK) {
                __syncthreads();                   // stage (c+2)%3 free to overwrite
                LOAD_CHUNK(gA, gB, c + 2, (c + 2) % NSTAGE);
                asm volatile("cp.async.wait_group 2;");
            } else if (c + 1 < NCHUNK) {
                asm volatile("cp.async.wait_group 1;");
            } else {
                asm volatile("cp.async.wait_group 0;");
            }
            __syncthreads();

            const uint32_t aBse = sbase + SM_A(c % NSTAGE);
            const uint32_t bBse = sbase + SM_B(c % NSTAGE);

            #pragma unroll
            for (int ks = 0; ks < 4; ks++) {       // 4 k16 steps per 64-half chunk
                uint32_t afr[2][4], bfr[4][4];
                #pragma unroll
                for (int t = 0; t < 2; t++) {
                    uint32_t addr = aBse + (uint32_t)(aRow + t * 16) * 128
                                  + (uint32_t)(((ks * 2 + aKhalf) ^ arow7) * 16);
                    ldm4(afr[t], addr);
                }
                #pragma unroll
                for (int nt = 0; nt < 4; nt++) {
                    uint32_t row = (uint32_t)(wn * 64 + nt * 16 + bRowIn);
                    uint32_t addr = bBse + row * 128
                                  + (uint32_t)(((ks * 2 + bKhalf) ^ brow7) * 16);
                    ldm4(bfr[nt], addr);
                }
                #pragma unroll
                for (int t = 0; t < 2; t++)
                    #pragma unroll
                    for (int nt = 0; nt < 4; nt++) {
                        mma16816(acc[t][nt * 2],     afr[t], &bfr[nt][0]);
                        mma16816(acc[t][nt * 2 + 1], afr[t], &bfr[nt][2]);
                    }
            }
        }

        // ---- prefetch next wave chunks 0,1 (stages 0,1 fully consumed) ----
        if (w + 1 < NWAVE) {
            const __half* gAn = g_A + (size_t)((w + 1) * NSTRIPW + sIdx) * BM * KD;
            LOAD_CHUNK(gAn, gB, 0, 0);
            LOAD_CHUNK(gAn, gB, 1, 1);
        }

        // ---- write raw log_dist tile + rowmax atomics ----
        #pragma unroll
        for (int t = 0; t < 2; t++) {
            const int r0 = m0 + wm * 32 + t * 16 + g;
            const int r1 = r0 + 8;
            float mx0 = -1e30f, mx1 = -1e30f;
            #pragma unroll
            for (int j = 0; j < 8; j++) {
                float v0 = acc[t][j][0] + BASEV;
                float v1 = acc[t][j][1] + BASEV;
                float v2 = acc[t][j][2] + BASEV;
                float v3 = acc[t][j][3] + BASEV;
                const int c2 = n0 + wn * 64 + j * 8 + q * 2;
                *reinterpret_cast<float2*>(out + (size_t)r0 * NT + c2) = make_float2(v0, v1);
                *reinterpret_cast<float2*>(out + (size_t)r1 * NT + c2) = make_float2(v2, v3);
                mx0 = fmaxf(mx0, fmaxf(v0, v1));
                mx1 = fmaxf(mx1, fmaxf(v2, v3));
            }
            mx0 = fmaxf(mx0, __shfl_xor_sync(0xffffffffu, mx0, 1));
            mx0 = fmaxf(mx0, __shfl_xor_sync(0xffffffffu, mx0, 2));
            mx1 = fmaxf(mx1, __shfl_xor_sync(0xffffffffu, mx1, 1));
            mx1 = fmaxf(mx1, __shfl_xor_sync(0xffffffffu, mx1, 2));
            if (q == 0) {
                atomicMax(&g_rowmax[r0], __float_as_uint(mx0 + 128.0f));
                atomicMax(&g_rowmax[r1], __float_as_uint(mx1 + 128.0f));
            }
        }

        // ---- signal tile completion (release) ----
        __threadfence();
        __syncthreads();
        if (tid == 0) atomicAdd(&g_done[strip], 1);

        // ---- fixup own tile of previous wave (lag-1, normally no wait) ----
        if (w >= 1) {
            FIXUP((w - 1) * NSTRIPW + sIdx);
        }
    }

    // ---- final wave's fixup ----
    FIXUP((NWAVE - 1) * NSTRIPW + sIdx);
}

// ============================================================================
// Launch
// ============================================================================
extern "C" void kernel_launch(void* const* d_in, const int* in_sizes, int n_in,
                              void* d_out, int out_size)
{
    const float* bw = (const float*)d_in[0];
    const float* te = (const float*)d_in[1];
    const float* tr = (const float*)d_in[2];
    float* out = (float*)d_out;

    cudaFuncSetAttribute(gemm_fused_kernel,
                         cudaFuncAttributeMaxDynamicSharedMemorySize, SMEM_TOTAL);

    pack_kernel<<<(NT * NF + 255) / 256, 256>>>(bw, te, tr);
    gemm_fused_kernel<<<GRID, 256, SMEM_TOTAL>>>(out);
}

// round 14
// speedup vs baseline: 1.2019x; 1.2019x over previous
#include <cuda_runtime.h>
#include <cuda_fp16.h>
#include <cstdint>
#include <cstddef>

// ============================================================================
// Problem constants
// ============================================================================
#define NT      8192            // n_test == n_train
#define NF      64              // n_feat
#define KD      384             // GEMM K = 64 feat * 3 Fourier dims * 2 (hi/lo)
#define BM      128             // CTA M tile
#define BN      128             // CTA N tile
#define BK      64              // halfs per K chunk (128 bytes/row)
#define NCHUNK  (KD / BK)       // 6
#define NSTAGE  3

#define NSTRIP  (NT / BM)       // 64 row strips
#define NCOLT   (NT / BN)       // 64 col tiles per strip
#define NSTRIPW 4               // strips per wave
#define GRID    (NSTRIPW * NCOLT)   // 256 CTAs, all resident (2/SM proven)
#define NWAVE   (NSTRIP / NSTRIPW)  // 16
#define CGTOT   (NWAVE * NCHUNK)    // 96 chunks, continuous pipeline

// SMEM: three stages of (A tile 16KB + B tile 16KB)
#define STAGE_BYTES (BM * 128 + BN * 128)           // 32768
#define SM_A(s)     ((s) * STAGE_BYTES)
#define SM_B(s)     ((s) * STAGE_BYTES + BM * 128)
#define SMEM_TOTAL  (NSTAGE * STAGE_BYTES)          // 98304 (x2 CTAs = 192KB/SM)

// ============================================================================
// Device scratch (no allocations allowed)
// ============================================================================
__device__ __align__(1024) __half g_A[(size_t)NT * KD];   // 6 MB Fourier pack (test, weighted)
__device__ __align__(1024) __half g_B[(size_t)NT * KD];   // 6 MB Fourier pack (train)
__device__ unsigned g_rowmax[NT];                          // bits of (rowmax_log + 128)
__device__ float    g_base;                                // -64*ln3 + 0.25*sum(w)
__device__ int      g_done[NSTRIP];                        // completed tiles per strip

// ============================================================================
// Helpers
// ============================================================================
__device__ __forceinline__ uint32_t smem_u32(const void* p) {
    uint32_t a;
    asm("{ .reg .u64 t; cvta.to.shared.u64 t, %1; cvt.u32.u64 %0, t; }"
        : "=r"(a) : "l"(p));
    return a;
}

__device__ __forceinline__ uint32_t sw128(uint32_t off) {
    return off ^ ((off >> 3) & 0x70u);
}

__device__ __forceinline__ void cp16(uint32_t smem_dst, const void* gmem_src) {
    asm volatile("cp.async.cg.shared.global [%0], [%1], 16;"
                 :: "r"(smem_dst), "l"(gmem_src) : "memory");
}

__device__ __forceinline__ void ldm4(uint32_t* r, uint32_t addr) {
    asm volatile("ldmatrix.sync.aligned.m8n8.x4.shared.b16 {%0,%1,%2,%3}, [%4];"
                 : "=r"(r[0]), "=r"(r[1]), "=r"(r[2]), "=r"(r[3]) : "r"(addr));
}

__device__ __forceinline__ void mma16816(float* d, const uint32_t* a, const uint32_t* b) {
    asm volatile(
        "mma.sync.aligned.m16n8k16.row.col.f32.f16.f16.f32 "
        "{%0,%1,%2,%3}, {%4,%5,%6,%7}, {%8,%9}, {%0,%1,%2,%3};"
        : "+f"(d[0]), "+f"(d[1]), "+f"(d[2]), "+f"(d[3])
        : "r"(a[0]), "r"(a[1]), "r"(a[2]), "r"(a[3]), "r"(b[0]), "r"(b[1]));
}

// sign-apply on fp16 bits: sgn in {-1,0,+1}
__device__ __forceinline__ unsigned short sgn16(unsigned short v, int sgn) {
    return sgn == 0 ? (unsigned short)0
                    : (sgn > 0 ? v : (unsigned short)(v ^ 0x8000u));
}

// ============================================================================
// Kernel 1: Fourier pack + state reset + base reduction  (proven R6-R13)
// ============================================================================
__global__ __launch_bounds__(256) void pack_kernel(
    const float* __restrict__ bw,
    const float* __restrict__ testX,
    const float* __restrict__ trainX)
{
    int idx = blockIdx.x * 256 + threadIdx.x;     // 0 .. NT*NF-1
    if (idx < NT) g_rowmax[idx] = 0u;             // stored values always > 0
    if (idx < NSTRIP) g_done[idx] = 0;

    __shared__ float sw[NF];
    if (blockIdx.x == 0) {
        if (threadIdx.x < NF) {
            float h = bw[threadIdx.x];
            sw[threadIdx.x] = logf(3.0f * (1.0f - h) / h);
        }
        __syncthreads();
        if (threadIdx.x == 0) {
            float s = 0.0f;
            #pragma unroll
            for (int f = 0; f < NF; f++) s += sw[f];
            g_base = -64.0f * 1.0986122886681098f + 0.25f * s;
        }
    }

    if (idx >= NT * NF) return;
    int i = idx >> 6;
    int f = idx & (NF - 1);

    float h = bw[f];
    float w = logf(3.0f * (1.0f - h) / h);        // log_true - log_false (> 0)
    float w2 = 0.5f * w, w4 = 0.25f * w;
    __half h2 = __float2half_rn(w2);
    unsigned short H2 = __half_as_ushort(h2);
    unsigned short L2 = __half_as_ushort(__float2half_rn(w2 - __half2float(h2)));
    __half h4 = __float2half_rn(w4);
    unsigned short H4 = __half_as_ushort(h4);
    unsigned short L4 = __half_as_ushort(__float2half_rn(w4 - __half2float(h4)));

    int t = (int)testX[idx];
    int s = (int)trainX[idx];

    int ct = (t == 0) ? 1 : ((t == 2) ? -1 : 0);
    int st = (t == 1) ? 1 : ((t == 3) ? -1 : 0);
    int pt = (t & 1) ? -1 : 1;
    int cs = (s == 0) ? 1 : ((s == 2) ? -1 : 0);
    int ss = (s == 1) ? 1 : ((s == 3) ? -1 : 0);
    int ps = (s & 1) ? -1 : 1;

    const unsigned short ONE = 0x3C00u;
    unsigned short a0 = sgn16(H2, ct), a1 = sgn16(L2, ct);
    unsigned short a2 = sgn16(H2, st), a3 = sgn16(L2, st);
    unsigned short a4 = sgn16(H4, pt), a5 = sgn16(L4, pt);
    unsigned short bc = sgn16(ONE, cs), bs = sgn16(ONE, ss), bp = sgn16(ONE, ps);

    uint32_t* pa = reinterpret_cast<uint32_t*>(
        reinterpret_cast<char*>(g_A) + (size_t)i * (KD * 2) + f * 12);
    uint32_t* pb = reinterpret_cast<uint32_t*>(
        reinterpret_cast<char*>(g_B) + (size_t)i * (KD * 2) + f * 12);
    pa[0] = (uint32_t)a0 | ((uint32_t)a1 << 16);
    pa[1] = (uint32_t)a2 | ((uint32_t)a3 << 16);
    pa[2] = (uint32_t)a4 | ((uint32_t)a5 << 16);
    pb[0] = (uint32_t)bc | ((uint32_t)bc << 16);
    pb[1] = (uint32_t)bs | ((uint32_t)bs << 16);
    pb[2] = (uint32_t)bp | ((uint32_t)bp << 16);
}

// ============================================================================
// Kernel 2: single-pass wave-synchronized GEMM + exp epilogue (R12 structure)
//   Continuous 96-chunk cp.async pipeline across all 16 waves,
//   ONE __syncthreads per chunk (wait_group -> barrier -> issue -> compute).
// ============================================================================
__global__ __launch_bounds__(256, 2) void gemm_fused_kernel(float* __restrict__ out)
{
    extern __shared__ __align__(1024) unsigned char smem[];
    __shared__ float s_rm[BM];
    const int tid  = threadIdx.x;
    const int wid  = tid >> 5;
    const int lane = tid & 31;
    const int wm   = wid >> 1;           // warp M index 0..3  (rows wm*32)
    const int wn   = wid & 1;            // warp N index 0..1  (cols wn*64)
    const int sIdx = blockIdx.x >> 6;    // strip-within-wave 0..3
    const int col  = blockIdx.x & 63;    // column tile (constant across waves)
    const int n0   = col * BN;

    const uint32_t sbase = smem_u32(smem);
    const float BASEV = g_base;
    const __half* gB = g_B + (size_t)n0 * KD;    // constant across waves

    #define LOAD_CHUNK(pA, pB, c, s)                                            \
    do {                                                                        \
        uint32_t aB = sbase + SM_A(s), bB = sbase + SM_B(s);                    \
        _Pragma("unroll")                                                       \
        for (int i = 0; i < 8; i++) {                                           \
            int u = tid + i * 256;                                              \
            if (u < 1024) {                                                     \
                int row = u >> 3, seg = u & 7;                                  \
                cp16(aB + sw128(row * 128 + seg * 16),                          \
                     (pA) + (size_t)row * KD + (c) * BK + seg * 8);             \
            } else {                                                            \
                int u2 = u - 1024;                                              \
                int row = u2 >> 3, seg = u2 & 7;                                \
                cp16(bB + sw128(row * 128 + seg * 16),                          \
                     (pB) + (size_t)row * KD + (c) * BK + seg * 8);             \
            }                                                                   \
        }                                                                       \
        asm volatile("cp.async.commit_group;");                                 \
    } while (0)

    // ---- per-lane ldmatrix geometry (proven R5-R13) ----
    const int aRow   = wm * 32 + ((lane >> 3) & 1) * 8 + (lane & 7);
    const int aKhalf = (lane >> 4) & 1;
    const int arow7  = aRow & 7;
    const int bRowIn = ((lane >> 4) & 1) * 8 + (lane & 7);
    const int bKhalf = (lane >> 3) & 1;
    const int brow7  = bRowIn & 7;
    const int g  = lane >> 2;
    const int q  = lane & 3;

    {   // prologue: chunks 0,1 of wave 0
        const __half* gA0 = g_A + (size_t)(sIdx * BM) * KD;
        LOAD_CHUNK(gA0, gB, 0, 0);
        LOAD_CHUNK(gA0, gB, 1, 1);
    }

    float acc[2][8][4];

    for (int cg = 0; cg < CGTOT; cg++) {
        const int c = cg % NCHUNK;
        const int w = cg / NCHUNK;

        if (c == 0) {
            #pragma unroll
            for (int t = 0; t < 2; t++)
                #pragma unroll
                for (int j = 0; j < 8; j++)
                    #pragma unroll
                    for (int v = 0; v < 4; v++) acc[t][j][v] = 0.0f;
        }

        // ---- wait for my chunk-cg loads, then one barrier ----
        if (cg < CGTOT - 1) {
            asm volatile("cp.async.wait_group 1;");
        } else {
            asm volatile("cp.async.wait_group 0;");
        }
        __syncthreads();    // everyone's chunk cg in smem; everyone done reading stage (cg+2)%3

        // ---- issue load for chunk cg+2 (possibly next wave's A) ----
        if (cg + 2 < CGTOT) {
            const int cgn = cg + 2;
            const __half* gAn = g_A
                + (size_t)((cgn / NCHUNK) * NSTRIPW + sIdx) * BM * KD;
            LOAD_CHUNK(gAn, gB, cgn % NCHUNK, cgn % NSTAGE);
        }

        // ---- compute chunk cg ----
        const uint32_t aBse = sbase + SM_A(cg % NSTAGE);
        const uint32_t bBse = sbase + SM_B(cg % NSTAGE);

        #pragma unroll
        for (int ks = 0; ks < 4; ks++) {           // 4 k16 steps per 64-half chunk
            uint32_t afr[2][4], bfr[4][4];
            #pragma unroll
            for (int t = 0; t < 2; t++) {
                uint32_t addr = aBse + (uint32_t)(aRow + t * 16) * 128
                              + (uint32_t)(((ks * 2 + aKhalf) ^ arow7) * 16);
                ldm4(afr[t], addr);
            }
            #pragma unroll
            for (int nt = 0; nt < 4; nt++) {
                uint32_t row = (uint32_t)(wn * 64 + nt * 16 + bRowIn);
                uint32_t addr = bBse + row * 128
                              + (uint32_t)(((ks * 2 + bKhalf) ^ brow7) * 16);
                ldm4(bfr[nt], addr);
            }
            #pragma unroll
            for (int t = 0; t < 2; t++)
                #pragma unroll
                for (int nt = 0; nt < 4; nt++) {
                    mma16816(acc[t][nt * 2],     afr[t], &bfr[nt][0]);
                    mma16816(acc[t][nt * 2 + 1], afr[t], &bfr[nt][2]);
                }
        }

        if (c != NCHUNK - 1) continue;

        // ================= wave epilogue (R12-proven) =================
        const int strip = w * NSTRIPW + sIdx;
        const int m0 = strip * BM;

        // ---- rowmax: local max -> shfl -> atomicMax ----
        #pragma unroll
        for (int t = 0; t < 2; t++) {
            float mx0 = -1e30f, mx1 = -1e30f;
            #pragma unroll
            for (int j = 0; j < 8; j++) {
                mx0 = fmaxf(mx0, fmaxf(acc[t][j][0], acc[t][j][1]));
                mx1 = fmaxf(mx1, fmaxf(acc[t][j][2], acc[t][j][3]));
            }
            mx0 = fmaxf(mx0, __shfl_xor_sync(0xffffffffu, mx0, 1));
            mx0 = fmaxf(mx0, __shfl_xor_sync(0xffffffffu, mx0, 2));
            mx1 = fmaxf(mx1, __shfl_xor_sync(0xffffffffu, mx1, 1));
            mx1 = fmaxf(mx1, __shfl_xor_sync(0xffffffffu, mx1, 2));
            if (q == 0) {
                const int r0 = m0 + wm * 32 + t * 16 + g;
                atomicMax(&g_rowmax[r0],     __float_as_uint(mx0 + BASEV + 128.0f));
                atomicMax(&g_rowmax[r0 + 8], __float_as_uint(mx1 + BASEV + 128.0f));
            }
        }

        // ---- strip barrier: wait for all 64 tiles of this strip ----
        __threadfence();
        __syncthreads();
        if (tid == 0) {
            atomicAdd(&g_done[strip], 1);
            while (atomicAdd(&g_done[strip], 0) < NCOLT) { }
            __threadfence();
        }
        __syncthreads();

        // ---- load finalized row maxima into smem (L2-coherent load) ----
        if (tid < BM) {
            unsigned bits = __ldcg(&g_rowmax[m0 + tid]);
            s_rm[tid] = __uint_as_float(bits) - 128.0f;
        }
        __syncthreads();

        // ---- write out = m * exp(x - m), straight from registers ----
        #pragma unroll
        for (int t = 0; t < 2; t++) {
            const int lr0 = wm * 32 + t * 16 + g;
            const int lr1 = lr0 + 8;
            const float m0v = s_rm[lr0];
            const float m1v = s_rm[lr1];
            float* orow0 = out + (size_t)(m0 + lr0) * NT + n0;
            float* orow1 = out + (size_t)(m0 + lr1) * NT + n0;
            #pragma unroll
            for (int j = 0; j < 8; j++) {
                float v0 = acc[t][j][0] + BASEV;
                float v1 = acc[t][j][1] + BASEV;
                float v2 = acc[t][j][2] + BASEV;
                float v3 = acc[t][j][3] + BASEV;
                const int c2 = wn * 64 + j * 8 + q * 2;
                *reinterpret_cast<float2*>(orow0 + c2) =
                    make_float2(m0v * __expf(v0 - m0v), m0v * __expf(v1 - m0v));
                *reinterpret_cast<float2*>(orow1 + c2) =
                    make_float2(m1v * __expf(v2 - m1v), m1v * __expf(v3 - m1v));
            }
        }
        // next iteration's top __syncthreads makes s_rm reuse safe
    }
}

// ============================================================================
// Launch
// ============================================================================
extern "C" void kernel_launch(void* const* d_in, const int* in_sizes, int n_in,
                              void* d_out, int out_size)
{
    const float* bw = (const float*)d_in[0];
    const float* te = (const float*)d_in[1];
    const float* tr = (const float*)d_in[2];
    float* out = (float*)d_out;

    cudaFuncSetAttribute(gemm_fused_kernel,
                         cudaFuncAttributeMaxDynamicSharedMemorySize, SMEM_TOTAL);

    pack_kernel<<<(NT * NF + 255) / 256, 256>>>(bw, te, tr);
    gemm_fused_kernel<<<GRID, 256, SMEM_TOTAL>>>(out);
}

// round 16
// speedup vs baseline: 1.2801x; 1.0651x over previous
#include <cuda_runtime.h>
#include <cuda_fp16.h>
#include <cstdint>
#include <cstddef>

// ============================================================================
// Problem constants
// ============================================================================
#define NT      8192            // n_test == n_train
#define NF      64              // n_feat
#define KD      384             // GEMM K = 64 feat * 3 Fourier dims * 2 (hi/lo)
#define BM      64              // CTA M tile (4-warp CTA)
#define BN      128             // CTA N tile
#define BK      64              // halfs per K chunk (128 bytes/row)
#define NCHUNK  (KD / BK)       // 6
#define NSTAGE  2
#define NTHR    128             // threads per CTA (4 warps)

#define NSTRIP  (NT / BM)       // 128 row strips
#define NCOLT   (NT / BN)       // 64 col tiles per strip
#define NGRP    8               // strip-groups
#define GRID    (NGRP * NCOLT)  // 512 CTAs, all resident (4/SM: smem+regs fit)
#define NWAVE   (NSTRIP / NGRP) // 16
#define CGTOT   (NWAVE * NCHUNK)// 96 chunks, continuous pipeline

// SMEM: two stages of (A tile 8KB + B tile 16KB)
#define STAGE_BYTES (BM * 128 + BN * 128)           // 24576
#define SM_A(s)     ((s) * STAGE_BYTES)
#define SM_B(s)     ((s) * STAGE_BYTES + BM * 128)
#define SMEM_TOTAL  (NSTAGE * STAGE_BYTES)          // 49152 (x4 CTAs = 192KB/SM)

// ============================================================================
// Device scratch (no allocations allowed)
// ============================================================================
__device__ __align__(1024) __half g_A[(size_t)NT * KD];   // 6 MB Fourier pack (test, weighted)
__device__ __align__(1024) __half g_B[(size_t)NT * KD];   // 6 MB Fourier pack (train)
__device__ unsigned g_rowmax[NT];                          // bits of (rowmax_log + 128)
__device__ float    g_base;                                // -64*ln3 + 0.25*sum(w)
__device__ int      g_done[NSTRIP];                        // completed tiles per strip

// ============================================================================
// Helpers
// ============================================================================
__device__ __forceinline__ uint32_t smem_u32(const void* p) {
    uint32_t a;
    asm("{ .reg .u64 t; cvta.to.shared.u64 t, %1; cvt.u32.u64 %0, t; }"
        : "=r"(a) : "l"(p));
    return a;
}

__device__ __forceinline__ uint32_t sw128(uint32_t off) {
    return off ^ ((off >> 3) & 0x70u);
}

__device__ __forceinline__ void cp16(uint32_t smem_dst, const void* gmem_src) {
    asm volatile("cp.async.cg.shared.global [%0], [%1], 16;"
                 :: "r"(smem_dst), "l"(gmem_src) : "memory");
}

__device__ __forceinline__ void ldm4(uint32_t* r, uint32_t addr) {
    asm volatile("ldmatrix.sync.aligned.m8n8.x4.shared.b16 {%0,%1,%2,%3}, [%4];"
                 : "=r"(r[0]), "=r"(r[1]), "=r"(r[2]), "=r"(r[3]) : "r"(addr));
}

__device__ __forceinline__ void mma16816(float* d, const uint32_t* a, const uint32_t* b) {
    asm volatile(
        "mma.sync.aligned.m16n8k16.row.col.f32.f16.f16.f32 "
        "{%0,%1,%2,%3}, {%4,%5,%6,%7}, {%8,%9}, {%0,%1,%2,%3};"
        : "+f"(d[0]), "+f"(d[1]), "+f"(d[2]), "+f"(d[3])
        : "r"(a[0]), "r"(a[1]), "r"(a[2]), "r"(a[3]), "r"(b[0]), "r"(b[1]));
}

// sign-apply on fp16 bits: sgn in {-1,0,+1}
__device__ __forceinline__ unsigned short sgn16(unsigned short v, int sgn) {
    return sgn == 0 ? (unsigned short)0
                    : (sgn > 0 ? v : (unsigned short)(v ^ 0x8000u));
}

// ============================================================================
// Kernel 1: Fourier pack + state reset + base reduction  (proven R6-R14)
// ============================================================================
__global__ __launch_bounds__(256) void pack_kernel(
    const float* __restrict__ bw,
    const float* __restrict__ testX,
    const float* __restrict__ trainX)
{
    int idx = blockIdx.x * 256 + threadIdx.x;     // 0 .. NT*NF-1
    if (idx < NT) g_rowmax[idx] = 0u;             // stored values always > 0
    if (idx < NSTRIP) g_done[idx] = 0;

    __shared__ float sw[NF];
    if (blockIdx.x == 0) {
        if (threadIdx.x < NF) {
            float h = bw[threadIdx.x];
            sw[threadIdx.x] = logf(3.0f * (1.0f - h) / h);
        }
        __syncthreads();
        if (threadIdx.x == 0) {
            float s = 0.0f;
            #pragma unroll
            for (int f = 0; f < NF; f++) s += sw[f];
            g_base = -64.0f * 1.0986122886681098f + 0.25f * s;
        }
    }

    if (idx >= NT * NF) return;
    int i = idx >> 6;
    int f = idx & (NF - 1);

    float h = bw[f];
    float w = logf(3.0f * (1.0f - h) / h);        // log_true - log_false (> 0)
    float w2 = 0.5f * w, w4 = 0.25f * w;
    __half h2 = __float2half_rn(w2);
    unsigned short H2 = __half_as_ushort(h2);
    unsigned short L2 = __half_as_ushort(__float2half_rn(w2 - __half2float(h2)));
    __half h4 = __float2half_rn(w4);
    unsigned short H4 = __half_as_ushort(h4);
    unsigned short L4 = __half_as_ushort(__float2half_rn(w4 - __half2float(h4)));

    int t = (int)testX[idx];
    int s = (int)trainX[idx];

    int ct = (t == 0) ? 1 : ((t == 2) ? -1 : 0);
    int st = (t == 1) ? 1 : ((t == 3) ? -1 : 0);
    int pt = (t & 1) ? -1 : 1;
    int cs = (s == 0) ? 1 : ((s == 2) ? -1 : 0);
    int ss = (s == 1) ? 1 : ((s == 3) ? -1 : 0);
    int ps = (s & 1) ? -1 : 1;

    const unsigned short ONE = 0x3C00u;
    unsigned short a0 = sgn16(H2, ct), a1 = sgn16(L2, ct);
    unsigned short a2 = sgn16(H2, st), a3 = sgn16(L2, st);
    unsigned short a4 = sgn16(H4, pt), a5 = sgn16(L4, pt);
    unsigned short bc = sgn16(ONE, cs), bs = sgn16(ONE, ss), bp = sgn16(ONE, ps);

    uint32_t* pa = reinterpret_cast<uint32_t*>(
        reinterpret_cast<char*>(g_A) + (size_t)i * (KD * 2) + f * 12);
    uint32_t* pb = reinterpret_cast<uint32_t*>(
        reinterpret_cast<char*>(g_B) + (size_t)i * (KD * 2) + f * 12);
    pa[0] = (uint32_t)a0 | ((uint32_t)a1 << 16);
    pa[1] = (uint32_t)a2 | ((uint32_t)a3 << 16);
    pa[2] = (uint32_t)a4 | ((uint32_t)a5 << 16);
    pb[0] = (uint32_t)bc | ((uint32_t)bc << 16);
    pb[1] = (uint32_t)bs | ((uint32_t)bs << 16);
    pb[2] = (uint32_t)bp | ((uint32_t)bp << 16);
}

// ============================================================================
// Kernel 2: single-pass wave-synchronized GEMM + exp epilogue
//   512 persistent 128-thread CTAs (4/SM), tile 64x128, warp tile 32x64.
//   16 waves; strip = wave*8 + group; R12-proven epilogue per strip.
// ============================================================================
__global__ __launch_bounds__(NTHR, 4) void gemm_fused_kernel(float* __restrict__ out)
{
    extern __shared__ __align__(1024) unsigned char smem[];
    __shared__ float s_rm[BM];
    const int tid  = threadIdx.x;
    const int wid  = tid >> 5;
    const int lane = tid & 31;
    const int wm   = wid >> 1;           // warp M index 0..1  (rows wm*32)
    const int wn   = wid & 1;            // warp N index 0..1  (cols wn*64)
    const int gid  = blockIdx.x >> 6;    // strip-group 0..7
    const int col  = blockIdx.x & 63;    // column tile (constant across waves)
    const int n0   = col * BN;

    const uint32_t sbase = smem_u32(smem);
    const float BASEV = g_base;
    const __half* gB = g_B + (size_t)n0 * KD;    // constant across waves

    // chunk loader: A 512 + B 1024 16B units, 12 per thread (128 threads)
    #define LOAD_CHUNK(pA, pB, c, s)                                            \
    do {                                                                        \
        uint32_t aB = sbase + SM_A(s), bB = sbase + SM_B(s);                    \
        _Pragma("unroll")                                                       \
        for (int i = 0; i < 12; i++) {                                          \
            int u = tid + i * NTHR;                                             \
            if (u < 512) {                                                      \
                int row = u >> 3, seg = u & 7;                                  \
                cp16(aB + sw128(row * 128 + seg * 16),                          \
                     (pA) + (size_t)row * KD + (c) * BK + seg * 8);             \
            } else {                                                            \
                int u2 = u - 512;                                               \
                int row = u2 >> 3, seg = u2 & 7;                                \
                cp16(bB + sw128(row * 128 + seg * 16),                          \
                     (pB) + (size_t)row * KD + (c) * BK + seg * 8);             \
            }                                                                   \
        }                                                                       \
        asm volatile("cp.async.commit_group;");                                 \
    } while (0)

    // ---- per-lane ldmatrix geometry (proven R5-R14, unchanged) ----
    const int aRow   = wm * 32 + ((lane >> 3) & 1) * 8 + (lane & 7);
    const int aKhalf = (lane >> 4) & 1;
    const int arow7  = aRow & 7;
    const int bRowIn = ((lane >> 4) & 1) * 8 + (lane & 7);
    const int bKhalf = (lane >> 3) & 1;
    const int brow7  = bRowIn & 7;
    const int g  = lane >> 2;
    const int q  = lane & 3;

    {   // prologue: chunk 0 of wave 0
        const __half* gA0 = g_A + (size_t)(gid * BM) * KD;
        LOAD_CHUNK(gA0, gB, 0, 0);
    }

    float acc[2][8][4];

    for (int cg = 0; cg < CGTOT; cg++) {
        const int c = cg % NCHUNK;
        const int w = cg / NCHUNK;

        if (c == 0) {
            #pragma unroll
            for (int t = 0; t < 2; t++)
                #pragma unroll
                for (int j = 0; j < 8; j++)
                    #pragma unroll
                    for (int v = 0; v < 4; v++) acc[t][j][v] = 0.0f;
        }

        // ---- issue load for chunk cg+1, then wait for chunk cg ----
        if (cg + 1 < CGTOT) {
            const int cgn = cg + 1;
            const __half* gAn = g_A
                + (size_t)((cgn / NCHUNK) * NGRP + gid) * BM * KD;
            LOAD_CHUNK(gAn, gB, cgn % NCHUNK, cgn & 1);
            asm volatile("cp.async.wait_group 1;");
        } else {
            asm volatile("cp.async.wait_group 0;");
        }
        __syncthreads();                          // chunk cg visible to all warps

        // ---- compute chunk cg ----
        const uint32_t aBse = sbase + SM_A(cg & 1);
        const uint32_t bBse = sbase + SM_B(cg & 1);

        #pragma unroll
        for (int ks = 0; ks < 4; ks++) {          // 4 k16 steps per 64-half chunk
            uint32_t afr[2][4], bfr[4][4];
            #pragma unroll
            for (int t = 0; t < 2; t++) {
                uint32_t addr = aBse + (uint32_t)(aRow + t * 16) * 128
                              + (uint32_t)(((ks * 2 + aKhalf) ^ arow7) * 16);
                ldm4(afr[t], addr);
            }
            #pragma unroll
            for (int nt = 0; nt < 4; nt++) {
                uint32_t row = (uint32_t)(wn * 64 + nt * 16 + bRowIn);
                uint32_t addr = bBse + row * 128
                              + (uint32_t)(((ks * 2 + bKhalf) ^ brow7) * 16);
                ldm4(bfr[nt], addr);
            }
            #pragma unroll
            for (int t = 0; t < 2; t++)
                #pragma unroll
                for (int nt = 0; nt < 4; nt++) {
                    mma16816(acc[t][nt * 2],     afr[t], &bfr[nt][0]);
                    mma16816(acc[t][nt * 2 + 1], afr[t], &bfr[nt][2]);
                }
        }

        if (c != NCHUNK - 1) {
            __syncthreads();                      // done reading stage cg&1
            continue;
        }

        // ================= wave epilogue (R12-proven) =================
        const int strip = w * NGRP + gid;
        const int m0 = strip * BM;

        // ---- rowmax: local max -> shfl -> atomicMax ----
        #pragma unroll
        for (int t = 0; t < 2; t++) {
            float mx0 = -1e30f, mx1 = -1e30f;
            #pragma unroll
            for (int j = 0; j < 8; j++) {
                mx0 = fmaxf(mx0, fmaxf(acc[t][j][0], acc[t][j][1]));
                mx1 = fmaxf(mx1, fmaxf(acc[t][j][2], acc[t][j][3]));
            }
            mx0 = fmaxf(mx0, __shfl_xor_sync(0xffffffffu, mx0, 1));
            mx0 = fmaxf(mx0, __shfl_xor_sync(0xffffffffu, mx0, 2));
            mx1 = fmaxf(mx1, __shfl_xor_sync(0xffffffffu, mx1, 1));
            mx1 = fmaxf(mx1, __shfl_xor_sync(0xffffffffu, mx1, 2));
            if (q == 0) {
                const int r0 = m0 + wm * 32 + t * 16 + g;
                atomicMax(&g_rowmax[r0],     __float_as_uint(mx0 + BASEV + 128.0f));
                atomicMax(&g_rowmax[r0 + 8], __float_as_uint(mx1 + BASEV + 128.0f));
            }
        }

        // ---- strip barrier: wait for all 64 tiles of this strip ----
        __threadfence();
        __syncthreads();
        if (tid == 0) {
            atomicAdd(&g_done[strip], 1);
            while (atomicAdd(&g_done[strip], 0) < NCOLT) { }
            __threadfence();
        }
        __syncthreads();

        // ---- load finalized row maxima into smem ----
        if (tid < BM) {
            unsigned bits = __ldcg(&g_rowmax[m0 + tid]);
            s_rm[tid] = __uint_as_float(bits) - 128.0f;
        }
        __syncthreads();

        // ---- write out = m * exp(x - m), straight from registers ----
        #pragma unroll
        for (int t = 0; t < 2; t++) {
            const int lr0 = wm * 32 + t * 16 + g;
            const int lr1 = lr0 + 8;
            const float m0v = s_rm[lr0];
            const float m1v = s_rm[lr1];
            float* orow0 = out + (size_t)(m0 + lr0) * NT + n0;
            float* orow1 = out + (size_t)(m0 + lr1) * NT + n0;
            #pragma unroll
            for (int j = 0; j < 8; j++) {
                float v0 = acc[t][j][0] + BASEV;
                float v1 = acc[t][j][1] + BASEV;
                float v2 = acc[t][j][2] + BASEV;
                float v3 = acc[t][j][3] + BASEV;
                const int c2 = wn * 64 + j * 8 + q * 2;
                *reinterpret_cast<float2*>(orow0 + c2) =
                    make_float2(m0v * __expf(v0 - m0v), m0v * __expf(v1 - m0v));
                *reinterpret_cast<float2*>(orow1 + c2) =
                    make_float2(m1v * __expf(v2 - m1v), m1v * __expf(v3 - m1v));
            }
        }
        __syncthreads();    // stage + s_rm reuse safe for next wave
    }
}

// ============================================================================
// Launch
// ============================================================================
extern "C" void kernel_launch(void* const* d_in, const int* in_sizes, int n_in,
                              void* d_out, int out_size)
{
    const float* bw = (const float*)d_in[0];
    const float* te = (const float*)d_in[1];
    const float* tr = (const float*)d_in[2];
    float* out = (float*)d_out;

    cudaFuncSetAttribute(gemm_fused_kernel,
                         cudaFuncAttributeMaxDynamicSharedMemorySize, SMEM_TOTAL);

    pack_kernel<<<(NT * NF + 255) / 256, 256>>>(bw, te, tr);
    gemm_fused_kernel<<<GRID, NTHR, SMEM_TOTAL>>>(out);
}

// round 17
// speedup vs baseline: 1.2805x; 1.0003x over previous
#include <cuda_runtime.h>
#include <cuda_fp16.h>
#include <cstdint>
#include <cstddef>

// ============================================================================
// Problem constants
// ============================================================================
#define NT      8192            // n_test == n_train
#define NF      64              // n_feat
#define KD      384             // GEMM K = 64 feat * 3 Fourier dims * 2 (hi/lo)
#define BM      64              // CTA M tile (4-warp CTA)
#define BN      128             // CTA N tile
#define BK      64              // halfs per K chunk (128 bytes/row)
#define NCHUNK  (KD / BK)       // 6
#define NSTAGE  2
#define NTHR    128             // threads per CTA (4 warps)

#define NSTRIP  (NT / BM)       // 128 row strips
#define NCOLT   (NT / BN)       // 64 col tiles per strip
#define NGRP    8               // strip-groups
#define GRID    (NGRP * NCOLT)  // 512 CTAs, all resident (4/SM: smem+regs fit)
#define NWAVE   (NSTRIP / NGRP) // 16
#define CGTOT   (NWAVE * NCHUNK)// 96 chunks, continuous pipeline

// group phase offset: co-resident CTAs (different groups) sit at different
// pipeline phases so epilogues/barrier-waits overlap other groups' GEMM
#define STRIP_OF(w, gid)  ((((w) + 2 * (gid)) & (NWAVE - 1)) * NGRP + (gid))

// SMEM: two stages of (A tile 8KB + B tile 16KB)
#define STAGE_BYTES (BM * 128 + BN * 128)           // 24576
#define SM_A(s)     ((s) * STAGE_BYTES)
#define SM_B(s)     ((s) * STAGE_BYTES + BM * 128)
#define SMEM_TOTAL  (NSTAGE * STAGE_BYTES)          // 49152 (x4 CTAs = 192KB/SM)

// ============================================================================
// Device scratch (no allocations allowed)
// ============================================================================
__device__ __align__(1024) __half g_A[(size_t)NT * KD];   // 6 MB Fourier pack (test, weighted)
__device__ __align__(1024) __half g_B[(size_t)NT * KD];   // 6 MB Fourier pack (train)
__device__ unsigned g_rowmax[NT];                          // bits of (rowmax_log + 128)
__device__ float    g_base;                                // -64*ln3 + 0.25*sum(w)
__device__ int      g_done[NSTRIP];                        // completed tiles per strip

// ============================================================================
// Helpers
// ============================================================================
__device__ __forceinline__ uint32_t smem_u32(const void* p) {
    uint32_t a;
    asm("{ .reg .u64 t; cvta.to.shared.u64 t, %1; cvt.u32.u64 %0, t; }"
        : "=r"(a) : "l"(p));
    return a;
}

__device__ __forceinline__ uint32_t sw128(uint32_t off) {
    return off ^ ((off >> 3) & 0x70u);
}

__device__ __forceinline__ void cp16(uint32_t smem_dst, const void* gmem_src) {
    asm volatile("cp.async.cg.shared.global [%0], [%1], 16;"
                 :: "r"(smem_dst), "l"(gmem_src) : "memory");
}

__device__ __forceinline__ void ldm4(uint32_t* r, uint32_t addr) {
    asm volatile("ldmatrix.sync.aligned.m8n8.x4.shared.b16 {%0,%1,%2,%3}, [%4];"
                 : "=r"(r[0]), "=r"(r[1]), "=r"(r[2]), "=r"(r[3]) : "r"(addr));
}

__device__ __forceinline__ void mma16816(float* d, const uint32_t* a, const uint32_t* b) {
    asm volatile(
        "mma.sync.aligned.m16n8k16.row.col.f32.f16.f16.f32 "
        "{%0,%1,%2,%3}, {%4,%5,%6,%7}, {%8,%9}, {%0,%1,%2,%3};"
        : "+f"(d[0]), "+f"(d[1]), "+f"(d[2]), "+f"(d[3])
        : "r"(a[0]), "r"(a[1]), "r"(a[2]), "r"(a[3]), "r"(b[0]), "r"(b[1]));
}

// sign-apply on fp16 bits: sgn in {-1,0,+1}
__device__ __forceinline__ unsigned short sgn16(unsigned short v, int sgn) {
    return sgn == 0 ? (unsigned short)0
                    : (sgn > 0 ? v : (unsigned short)(v ^ 0x8000u));
}

// ============================================================================
// Kernel 1: Fourier pack + state reset + base reduction  (proven R6-R16)
// ============================================================================
__global__ __launch_bounds__(256) void pack_kernel(
    const float* __restrict__ bw,
    const float* __restrict__ testX,
    const float* __restrict__ trainX)
{
    int idx = blockIdx.x * 256 + threadIdx.x;     // 0 .. NT*NF-1
    if (idx < NT) g_rowmax[idx] = 0u;             // stored values always > 0
    if (idx < NSTRIP) g_done[idx] = 0;

    __shared__ float sw[NF];
    if (blockIdx.x == 0) {
        if (threadIdx.x < NF) {
            float h = bw[threadIdx.x];
            sw[threadIdx.x] = logf(3.0f * (1.0f - h) / h);
        }
        __syncthreads();
        if (threadIdx.x == 0) {
            float s = 0.0f;
            #pragma unroll
            for (int f = 0; f < NF; f++) s += sw[f];
            g_base = -64.0f * 1.0986122886681098f + 0.25f * s;
        }
    }

    if (idx >= NT * NF) return;
    int i = idx >> 6;
    int f = idx & (NF - 1);

    float h = bw[f];
    float w = logf(3.0f * (1.0f - h) / h);        // log_true - log_false (> 0)
    float w2 = 0.5f * w, w4 = 0.25f * w;
    __half h2 = __float2half_rn(w2);
    unsigned short H2 = __half_as_ushort(h2);
    unsigned short L2 = __half_as_ushort(__float2half_rn(w2 - __half2float(h2)));
    __half h4 = __float2half_rn(w4);
    unsigned short H4 = __half_as_ushort(h4);
    unsigned short L4 = __half_as_ushort(__float2half_rn(w4 - __half2float(h4)));

    int t = (int)testX[idx];
    int s = (int)trainX[idx];

    int ct = (t == 0) ? 1 : ((t == 2) ? -1 : 0);
    int st = (t == 1) ? 1 : ((t == 3) ? -1 : 0);
    int pt = (t & 1) ? -1 : 1;
    int cs = (s == 0) ? 1 : ((s == 2) ? -1 : 0);
    int ss = (s == 1) ? 1 : ((s == 3) ? -1 : 0);
    int ps = (s & 1) ? -1 : 1;

    const unsigned short ONE = 0x3C00u;
    unsigned short a0 = sgn16(H2, ct), a1 = sgn16(L2, ct);
    unsigned short a2 = sgn16(H2, st), a3 = sgn16(L2, st);
    unsigned short a4 = sgn16(H4, pt), a5 = sgn16(L4, pt);
    unsigned short bc = sgn16(ONE, cs), bs = sgn16(ONE, ss), bp = sgn16(ONE, ps);

    uint32_t* pa = reinterpret_cast<uint32_t*>(
        reinterpret_cast<char*>(g_A) + (size_t)i * (KD * 2) + f * 12);
    uint32_t* pb = reinterpret_cast<uint32_t*>(
        reinterpret_cast<char*>(g_B) + (size_t)i * (KD * 2) + f * 12);
    pa[0] = (uint32_t)a0 | ((uint32_t)a1 << 16);
    pa[1] = (uint32_t)a2 | ((uint32_t)a3 << 16);
    pa[2] = (uint32_t)a4 | ((uint32_t)a5 << 16);
    pb[0] = (uint32_t)bc | ((uint32_t)bc << 16);
    pb[1] = (uint32_t)bs | ((uint32_t)bs << 16);
    pb[2] = (uint32_t)bp | ((uint32_t)bp << 16);
}

// ============================================================================
// Kernel 2: single-pass wave-synchronized GEMM + exp epilogue
//   512 persistent 128-thread CTAs (4/SM), tile 64x128, warp tile 32x64.
//   Group-phase-offset strips; ONE barrier per chunk (2-stage pipeline).
// ============================================================================
__global__ __launch_bounds__(NTHR, 4) void gemm_fused_kernel(float* __restrict__ out)
{
    extern __shared__ __align__(1024) unsigned char smem[];
    __shared__ float s_rm[BM];
    const int tid  = threadIdx.x;
    const int wid  = tid >> 5;
    const int lane = tid & 31;
    const int wm   = wid >> 1;           // warp M index 0..1  (rows wm*32)
    const int wn   = wid & 1;            // warp N index 0..1  (cols wn*64)
    const int gid  = blockIdx.x >> 6;    // strip-group 0..7
    const int col  = blockIdx.x & 63;    // column tile (constant across waves)
    const int n0   = col * BN;

    const uint32_t sbase = smem_u32(smem);
    const float BASEV = g_base;
    const __half* gB = g_B + (size_t)n0 * KD;    // constant across waves

    // chunk loader: A 512 + B 1024 16B units, 12 per thread (128 threads)
    #define LOAD_CHUNK(pA, pB, c, s)                                            \
    do {                                                                        \
        uint32_t aB = sbase + SM_A(s), bB = sbase + SM_B(s);                    \
        _Pragma("unroll")                                                       \
        for (int i = 0; i < 12; i++) {                                          \
            int u = tid + i * NTHR;                                             \
            if (u < 512) {                                                      \
                int row = u >> 3, seg = u & 7;                                  \
                cp16(aB + sw128(row * 128 + seg * 16),                          \
                     (pA) + (size_t)row * KD + (c) * BK + seg * 8);             \
            } else {                                                            \
                int u2 = u - 512;                                               \
                int row = u2 >> 3, seg = u2 & 7;                                \
                cp16(bB + sw128(row * 128 + seg * 16),                          \
                     (pB) + (size_t)row * KD + (c) * BK + seg * 8);             \
            }                                                                   \
        }                                                                       \
        asm volatile("cp.async.commit_group;");                                 \
    } while (0)

    // ---- per-lane ldmatrix geometry (proven R5-R16, unchanged) ----
    const int aRow   = wm * 32 + ((lane >> 3) & 1) * 8 + (lane & 7);
    const int aKhalf = (lane >> 4) & 1;
    const int arow7  = aRow & 7;
    const int bRowIn = ((lane >> 4) & 1) * 8 + (lane & 7);
    const int bKhalf = (lane >> 3) & 1;
    const int brow7  = bRowIn & 7;
    const int g  = lane >> 2;
    const int q  = lane & 3;

    {   // prologue: chunk 0 of this group's first strip
        const __half* gA0 = g_A + (size_t)STRIP_OF(0, gid) * BM * KD;
        LOAD_CHUNK(gA0, gB, 0, 0);
    }

    float acc[2][8][4];

    for (int cg = 0; cg < CGTOT; cg++) {
        const int c = cg % NCHUNK;
        const int w = cg / NCHUNK;

        if (c == 0) {
            #pragma unroll
            for (int t = 0; t < 2; t++)
                #pragma unroll
                for (int j = 0; j < 8; j++)
                    #pragma unroll
                    for (int v = 0; v < 4; v++) acc[t][j][v] = 0.0f;
        }

        // ---- single barrier: chunk cg visible AND stage (cg+1)&1 free ----
        asm volatile("cp.async.wait_group 0;");
        __syncthreads();

        // ---- issue load for chunk cg+1 (overlaps compute + epilogue) ----
        if (cg + 1 < CGTOT) {
            const int cgn = cg + 1;
            const __half* gAn = g_A
                + (size_t)STRIP_OF(cgn / NCHUNK, gid) * BM * KD;
            LOAD_CHUNK(gAn, gB, cgn % NCHUNK, cgn & 1);
        }

        // ---- compute chunk cg ----
        const uint32_t aBse = sbase + SM_A(cg & 1);
        const uint32_t bBse = sbase + SM_B(cg & 1);

        #pragma unroll
        for (int ks = 0; ks < 4; ks++) {          // 4 k16 steps per 64-half chunk
            uint32_t afr[2][4], bfr[4][4];
            #pragma unroll
            for (int t = 0; t < 2; t++) {
                uint32_t addr = aBse + (uint32_t)(aRow + t * 16) * 128
                              + (uint32_t)(((ks * 2 + aKhalf) ^ arow7) * 16);
                ldm4(afr[t], addr);
            }
            #pragma unroll
            for (int nt = 0; nt < 4; nt++) {
                uint32_t row = (uint32_t)(wn * 64 + nt * 16 + bRowIn);
                uint32_t addr = bBse + row * 128
                              + (uint32_t)(((ks * 2 + bKhalf) ^ brow7) * 16);
                ldm4(bfr[nt], addr);
            }
            #pragma unroll
            for (int t = 0; t < 2; t++)
                #pragma unroll
                for (int nt = 0; nt < 4; nt++) {
                    mma16816(acc[t][nt * 2],     afr[t], &bfr[nt][0]);
                    mma16816(acc[t][nt * 2 + 1], afr[t], &bfr[nt][2]);
                }
        }

        if (c != NCHUNK - 1) continue;

        // ================= wave epilogue (R12-proven) =================
        const int strip = STRIP_OF(w, gid);
        const int m0 = strip * BM;

        // ---- rowmax: local max -> shfl -> atomicMax ----
        #pragma unroll
        for (int t = 0; t < 2; t++) {
            float mx0 = -1e30f, mx1 = -1e30f;
            #pragma unroll
            for (int j = 0; j < 8; j++) {
                mx0 = fmaxf(mx0, fmaxf(acc[t][j][0], acc[t][j][1]));
                mx1 = fmaxf(mx1, fmaxf(acc[t][j][2], acc[t][j][3]));
            }
            mx0 = fmaxf(mx0, __shfl_xor_sync(0xffffffffu, mx0, 1));
            mx0 = fmaxf(mx0, __shfl_xor_sync(0xffffffffu, mx0, 2));
            mx1 = fmaxf(mx1, __shfl_xor_sync(0xffffffffu, mx1, 1));
            mx1 = fmaxf(mx1, __shfl_xor_sync(0xffffffffu, mx1, 2));
            if (q == 0) {
                const int r0 = m0 + wm * 32 + t * 16 + g;
                atomicMax(&g_rowmax[r0],     __float_as_uint(mx0 + BASEV + 128.0f));
                atomicMax(&g_rowmax[r0 + 8], __float_as_uint(mx1 + BASEV + 128.0f));
            }
        }

        // ---- strip barrier: wait for all 64 tiles of this strip ----
        __threadfence();
        __syncthreads();
        if (tid == 0) {
            atomicAdd(&g_done[strip], 1);
            while (atomicAdd(&g_done[strip], 0) < NCOLT) { }
            __threadfence();
        }
        __syncthreads();

        // ---- load finalized row maxima into smem ----
        if (tid < BM) {
            unsigned bits = __ldcg(&g_rowmax[m0 + tid]);
            s_rm[tid] = __uint_as_float(bits) - 128.0f;
        }
        __syncthreads();

        // ---- write out = m * exp(x - m), straight from registers ----
        #pragma unroll
        for (int t = 0; t < 2; t++) {
            const int lr0 = wm * 32 + t * 16 + g;
            const int lr1 = lr0 + 8;
            const float m0v = s_rm[lr0];
            const float m1v = s_rm[lr1];
            float* orow0 = out + (size_t)(m0 + lr0) * NT + n0;
            float* orow1 = out + (size_t)(m0 + lr1) * NT + n0;
            #pragma unroll
            for (int j = 0; j < 8; j++) {
                float v0 = acc[t][j][0] + BASEV;
                float v1 = acc[t][j][1] + BASEV;
                float v2 = acc[t][j][2] + BASEV;
                float v3 = acc[t][j][3] + BASEV;
                const int c2 = wn * 64 + j * 8 + q * 2;
                *reinterpret_cast<float2*>(orow0 + c2) =
                    make_float2(m0v * __expf(v0 - m0v), m0v * __expf(v1 - m0v));
                *reinterpret_cast<float2*>(orow1 + c2) =
                    make_float2(m1v * __expf(v2 - m1v), m1v * __expf(v3 - m1v));
            }
        }
        // next chunk's top __syncthreads makes s_rm + stage reuse safe
    }
}

// ============================================================================
// Launch
// ============================================================================
extern "C" void kernel_launch(void* const* d_in, const int* in_sizes, int n_in,
                              void* d_out, int out_size)
{
    const float* bw = (const float*)d_in[0];
    const float* te = (const float*)d_in[1];
    const float* tr = (const float*)d_in[2];
    float* out = (float*)d_out;

    cudaFuncSetAttribute(gemm_fused_kernel,
                         cudaFuncAttributeMaxDynamicSharedMemorySize, SMEM_TOTAL);

    pack_kernel<<<(NT * NF + 255) / 256, 256>>>(bw, te, tr);
    gemm_fused_kernel<<<GRID, NTHR, SMEM_TOTAL>>>(out);
}